// round 1
// baseline (speedup 1.0000x reference)
#include <cuda_runtime.h>
#include <math.h>

// Problem constants (fixed shapes for this bench)
#define N_NODES   2048
#define N_CHILD   4096
#define NNZ_PER   32768
#define NNZ_TOT   (2 * NNZ_PER)
#define G         4            // samples per compute block
#define NTHREADS  256

// ---------------- static device scratch (no allocations allowed) -------------
__device__ int2  g_csr[NNZ_TOT];        // {merged_col, exp(w) bits}
__device__ int   g_row_ptr[N_NODES + 1];
__device__ int   g_cnt[N_NODES];
__device__ int   g_fill[N_NODES];
__device__ float g_z[N_NODES];
__device__ float g_logz[N_NODES];

// ---------------- prep kernels ----------------------------------------------
__global__ void k_zero() {
    int i = blockIdx.x * blockDim.x + threadIdx.x;
    if (i < N_NODES) { g_cnt[i] = 0; g_fill[i] = 0; g_z[i] = 0.f; }
}

__global__ void k_hist(const int* __restrict__ r0, const float* __restrict__ d0,
                       const int* __restrict__ r1, const float* __restrict__ d1) {
    int k = blockIdx.x * blockDim.x + threadIdx.x;
    if (k >= NNZ_TOT) return;
    int row; float w;
    if (k < NNZ_PER) { row = r0[k];            w = d0[k]; }
    else             { row = r1[k - NNZ_PER];  w = d1[k - NNZ_PER]; }
    atomicAdd(&g_cnt[row], 1);
    atomicAdd(&g_z[row], __expf(w));
}

// single block, 1024 threads: Hillis-Steele inclusive scan over 2048 counters,
// plus log of normalization constants.
__global__ void k_scan() {
    __shared__ int a[N_NODES];
    __shared__ int b[N_NODES];
    int t = threadIdx.x;
    a[t] = g_cnt[t];
    a[t + 1024] = g_cnt[t + 1024];
    __syncthreads();
    int* src = a; int* dst = b;
    for (int off = 1; off < N_NODES; off <<= 1) {
        #pragma unroll
        for (int j = 0; j < 2; ++j) {
            int i = t + j * 1024;
            int v = src[i];
            if (i >= off) v += src[i - off];
            dst[i] = v;
        }
        __syncthreads();
        int* tmp = src; src = dst; dst = tmp;
    }
    #pragma unroll
    for (int j = 0; j < 2; ++j) {
        int i = t + j * 1024;
        g_row_ptr[i + 1] = src[i];
        g_logz[i] = __logf(g_z[i]);
    }
    if (t == 0) g_row_ptr[0] = 0;
}

__global__ void k_scatter(const int* __restrict__ r0, const int* __restrict__ c0,
                          const float* __restrict__ d0,
                          const int* __restrict__ r1, const int* __restrict__ c1,
                          const float* __restrict__ d1) {
    int k = blockIdx.x * blockDim.x + threadIdx.x;
    if (k >= NNZ_TOT) return;
    int row, col; float w;
    if (k < NNZ_PER) { row = r0[k]; col = c0[k];                 w = d0[k]; }
    else { int j = k - NNZ_PER; row = r1[j]; col = c1[j] + N_CHILD; w = d1[j]; }
    int pos = g_row_ptr[row] + atomicAdd(&g_fill[row], 1);
    g_csr[pos] = make_int2(col, __float_as_int(__expf(w)));
}

// ---------------- main compute kernel ----------------------------------------
// One block = G=4 samples. exp(ll) for the 8192 merged child columns sits in
// smem as float4 (one lane per sample) = 128 KB. Each thread owns 8 rows and
// does register-accumulated CSR segment sums (no atomics).
__global__ void __launch_bounds__(NTHREADS, 1)
k_main(const float* __restrict__ ll0, const float* __restrict__ ll1,
       float* __restrict__ out) {
    extern __shared__ float4 ell[];   // [2 * N_CHILD]
    const int tid = threadIdx.x;
    const long long s0 = (long long)blockIdx.x * G;
    const float* p0 = ll0 + s0 * N_CHILD;
    const float* p1 = ll1 + s0 * N_CHILD;

    // load + exponentiate the 4 ll rows of each child layer (coalesced)
    for (int i = tid; i < N_CHILD; i += NTHREADS) {
        float4 v;
        v.x = __expf(p0[i]);
        v.y = __expf(p0[i + N_CHILD]);
        v.z = __expf(p0[i + 2 * N_CHILD]);
        v.w = __expf(p0[i + 3 * N_CHILD]);
        ell[i] = v;
        float4 u;
        u.x = __expf(p1[i]);
        u.y = __expf(p1[i + N_CHILD]);
        u.z = __expf(p1[i + 2 * N_CHILD]);
        u.w = __expf(p1[i + 3 * N_CHILD]);
        ell[N_CHILD + i] = u;
    }
    __syncthreads();

    for (int r = tid; r < N_NODES; r += NTHREADS) {
        int k   = g_row_ptr[r];
        int end = g_row_ptr[r + 1];
        float4 acc = make_float4(0.f, 0.f, 0.f, 0.f);
        #pragma unroll 4
        for (; k < end; ++k) {
            int2 e  = __ldg(&g_csr[k]);
            float w = __int_as_float(e.y);
            float4 v = ell[e.x];
            acc.x = fmaf(v.x, w, acc.x);
            acc.y = fmaf(v.y, w, acc.y);
            acc.z = fmaf(v.z, w, acc.z);
            acc.w = fmaf(v.w, w, acc.w);
        }
        float lz = g_logz[r];
        float* o = out + s0 * N_NODES + r;
        o[0]           = __logf(acc.x) - lz;
        o[N_NODES]     = __logf(acc.y) - lz;
        o[2 * N_NODES] = __logf(acc.z) - lz;
        o[3 * N_NODES] = __logf(acc.w) - lz;
    }
}

// ---------------- launch ------------------------------------------------------
extern "C" void kernel_launch(void* const* d_in, const int* in_sizes, int n_in,
                              void* d_out, int out_size) {
    const float* ll0 = (const float*)d_in[0];
    const float* ll1 = (const float*)d_in[1];
    const float* w0d = (const float*)d_in[2];
    const float* w1d = (const float*)d_in[3];
    const int*   w0r = (const int*)d_in[4];
    const int*   w0c = (const int*)d_in[5];
    const int*   w1r = (const int*)d_in[6];
    const int*   w1c = (const int*)d_in[7];
    float* out = (float*)d_out;

    const int S = in_sizes[0] / N_CHILD;   // 4096

    const int smem_bytes = 2 * N_CHILD * (int)sizeof(float4);  // 128 KB
    cudaFuncSetAttribute(k_main, cudaFuncAttributeMaxDynamicSharedMemorySize,
                         smem_bytes);

    k_zero<<<(N_NODES + 255) / 256, 256>>>();
    k_hist<<<(NNZ_TOT + 255) / 256, 256>>>(w0r, w0d, w1r, w1d);
    k_scan<<<1, 1024>>>();
    k_scatter<<<(NNZ_TOT + 255) / 256, 256>>>(w0r, w0c, w0d, w1r, w1c, w1d);
    k_main<<<S / G, NTHREADS, smem_bytes>>>(ll0, ll1, out);
}

// round 2
// speedup vs baseline: 1.7330x; 1.7330x over previous
#include <cuda_runtime.h>
#include <cuda_fp16.h>
#include <math.h>

// Problem constants (fixed shapes for this bench)
#define N_NODES   2048
#define N_CHILD   4096
#define NNZ_PER   32768
#define NNZ_TOT   (2 * NNZ_PER)
#define G         4            // samples per compute block
#define NTHREADS  512

// ---------------- static device scratch (no allocations allowed) -------------
__device__ unsigned g_csrp[NNZ_TOT];     // (merged_col << 16) | fp16bits(exp(w))
__device__ int   g_row_ptr[N_NODES + 1];
__device__ int   g_cnt[N_NODES];
__device__ int   g_fill[N_NODES];
__device__ float g_z[N_NODES];
__device__ float g_logz[N_NODES];

// ---------------- prep kernels ----------------------------------------------
__global__ void k_zero() {
    int i = blockIdx.x * blockDim.x + threadIdx.x;
    if (i < N_NODES) { g_cnt[i] = 0; g_fill[i] = 0; g_z[i] = 0.f; }
}

__global__ void k_hist(const int* __restrict__ r0, const float* __restrict__ d0,
                       const int* __restrict__ r1, const float* __restrict__ d1) {
    int k = blockIdx.x * blockDim.x + threadIdx.x;
    if (k >= NNZ_TOT) return;
    int row; float w;
    if (k < NNZ_PER) { row = r0[k];            w = d0[k]; }
    else             { row = r1[k - NNZ_PER];  w = d1[k - NNZ_PER]; }
    atomicAdd(&g_cnt[row], 1);
    atomicAdd(&g_z[row], __expf(w));
}

// single block, 1024 threads: Hillis-Steele inclusive scan over 2048 counters,
// plus log of normalization constants.
__global__ void k_scan() {
    __shared__ int a[N_NODES];
    __shared__ int b[N_NODES];
    int t = threadIdx.x;
    a[t] = g_cnt[t];
    a[t + 1024] = g_cnt[t + 1024];
    __syncthreads();
    int* src = a; int* dst = b;
    for (int off = 1; off < N_NODES; off <<= 1) {
        #pragma unroll
        for (int j = 0; j < 2; ++j) {
            int i = t + j * 1024;
            int v = src[i];
            if (i >= off) v += src[i - off];
            dst[i] = v;
        }
        __syncthreads();
        int* tmp = src; src = dst; dst = tmp;
    }
    #pragma unroll
    for (int j = 0; j < 2; ++j) {
        int i = t + j * 1024;
        g_row_ptr[i + 1] = src[i];
        g_logz[i] = __logf(g_z[i]);
    }
    if (t == 0) g_row_ptr[0] = 0;
}

__global__ void k_scatter(const int* __restrict__ r0, const int* __restrict__ c0,
                          const float* __restrict__ d0,
                          const int* __restrict__ r1, const int* __restrict__ c1,
                          const float* __restrict__ d1) {
    int k = blockIdx.x * blockDim.x + threadIdx.x;
    if (k >= NNZ_TOT) return;
    int row, col; float w;
    if (k < NNZ_PER) { row = r0[k]; col = c0[k];                 w = d0[k]; }
    else { int j = k - NNZ_PER; row = r1[j]; col = c1[j] + N_CHILD; w = d1[j]; }
    int pos = g_row_ptr[row] + atomicAdd(&g_fill[row], 1);
    unsigned h = (unsigned)__half_as_ushort(__float2half_rn(__expf(w)));
    g_csrp[pos] = ((unsigned)col << 16) | h;
}

// ---------------- main compute kernel ----------------------------------------
// One block = G=4 samples. exp(ll) for the 8192 merged child columns sits in
// smem as half4 (one fp16 lane per sample) = 64 KB -> 2 CTAs/SM, 32 warps/SM.
// Each thread owns 4 rows; fp32 register accumulation (no atomics).
__global__ void __launch_bounds__(NTHREADS, 2)
k_main(const float* __restrict__ ll0, const float* __restrict__ ll1,
       float* __restrict__ out) {
    extern __shared__ uint2 ell[];   // [2 * N_CHILD], half4 per entry
    const int tid = threadIdx.x;
    const long long s0 = (long long)blockIdx.x * G;
    const float* p0 = ll0 + s0 * N_CHILD;
    const float* p1 = ll1 + s0 * N_CHILD;

    // load + exponentiate the 4 ll rows of each child layer (coalesced),
    // convert to half4 in smem
    for (int i = tid; i < N_CHILD; i += NTHREADS) {
        float a0 = __expf(p0[i]);
        float a1 = __expf(p0[i + N_CHILD]);
        float a2 = __expf(p0[i + 2 * N_CHILD]);
        float a3 = __expf(p0[i + 3 * N_CHILD]);
        __half2 h01 = __floats2half2_rn(a0, a1);
        __half2 h23 = __floats2half2_rn(a2, a3);
        ell[i] = make_uint2(*(unsigned*)&h01, *(unsigned*)&h23);

        float b0 = __expf(p1[i]);
        float b1 = __expf(p1[i + N_CHILD]);
        float b2 = __expf(p1[i + 2 * N_CHILD]);
        float b3 = __expf(p1[i + 3 * N_CHILD]);
        __half2 g01 = __floats2half2_rn(b0, b1);
        __half2 g23 = __floats2half2_rn(b2, b3);
        ell[N_CHILD + i] = make_uint2(*(unsigned*)&g01, *(unsigned*)&g23);
    }
    __syncthreads();

    for (int r = tid; r < N_NODES; r += NTHREADS) {
        int k   = g_row_ptr[r];
        int end = g_row_ptr[r + 1];
        float4 acc = make_float4(0.f, 0.f, 0.f, 0.f);
        #pragma unroll 4
        for (; k < end; ++k) {
            unsigned e = __ldg(&g_csrp[k]);
            float w = __half2float(__ushort_as_half((unsigned short)(e & 0xFFFFu)));
            uint2 hv = ell[e >> 16];
            float2 v01 = __half22float2(*(__half2*)&hv.x);
            float2 v23 = __half22float2(*(__half2*)&hv.y);
            acc.x = fmaf(v01.x, w, acc.x);
            acc.y = fmaf(v01.y, w, acc.y);
            acc.z = fmaf(v23.x, w, acc.z);
            acc.w = fmaf(v23.y, w, acc.w);
        }
        float lz = g_logz[r];
        float* o = out + s0 * N_NODES + r;
        o[0]           = __logf(acc.x) - lz;
        o[N_NODES]     = __logf(acc.y) - lz;
        o[2 * N_NODES] = __logf(acc.z) - lz;
        o[3 * N_NODES] = __logf(acc.w) - lz;
    }
}

// ---------------- launch ------------------------------------------------------
extern "C" void kernel_launch(void* const* d_in, const int* in_sizes, int n_in,
                              void* d_out, int out_size) {
    const float* ll0 = (const float*)d_in[0];
    const float* ll1 = (const float*)d_in[1];
    const float* w0d = (const float*)d_in[2];
    const float* w1d = (const float*)d_in[3];
    const int*   w0r = (const int*)d_in[4];
    const int*   w0c = (const int*)d_in[5];
    const int*   w1r = (const int*)d_in[6];
    const int*   w1c = (const int*)d_in[7];
    float* out = (float*)d_out;

    const int S = in_sizes[0] / N_CHILD;   // 4096

    const int smem_bytes = 2 * N_CHILD * (int)sizeof(uint2);  // 64 KB
    cudaFuncSetAttribute(k_main, cudaFuncAttributeMaxDynamicSharedMemorySize,
                         smem_bytes);

    k_zero<<<(N_NODES + 255) / 256, 256>>>();
    k_hist<<<(NNZ_TOT + 255) / 256, 256>>>(w0r, w0d, w1r, w1d);
    k_scan<<<1, 1024>>>();
    k_scatter<<<(NNZ_TOT + 255) / 256, 256>>>(w0r, w0c, w0d, w1r, w1c, w1d);
    k_main<<<S / G, NTHREADS, smem_bytes>>>(ll0, ll1, out);
}

// round 3
// speedup vs baseline: 2.5545x; 1.4740x over previous
#include <cuda_runtime.h>
#include <cuda_fp16.h>

// Fixed problem shapes
#define N_NODES   2048
#define N_CHILD   4096
#define NNZ_PER   32768
#define NNZ_TOT   (2 * NNZ_PER)
#define G         4                 // samples per compute block
#define NTHREADS  512
#define NWARPS    (NTHREADS / 32)   // 16
#define NGROUPS   (N_NODES / 32)    // 64 row-groups (one warp each)
#define MAXPAD    160               // >> Poisson(32) group max; safety margin
#define PAD_ENTRIES (NGROUPS * 32 * MAXPAD)

// ---------------- static device scratch -------------------------------------
__device__ unsigned g_pad[PAD_ENTRIES];  // SELL-32: (col<<16)|fp16(exp(w)), 0 = pad
__device__ int   g_fill[N_NODES];
__device__ int   g_grouplen[NGROUPS];
__device__ float g_z[N_NODES];
__device__ float g_logz[N_NODES];

// ---------------- prep kernels ----------------------------------------------
__global__ void k_zero() {
    int i = blockIdx.x * blockDim.x + threadIdx.x;
    int stride = gridDim.x * blockDim.x;
    uint4* p4 = (uint4*)g_pad;
    for (int k = i; k < PAD_ENTRIES / 4; k += stride)
        p4[k] = make_uint4(0u, 0u, 0u, 0u);
    if (i < N_NODES) { g_fill[i] = 0; g_z[i] = 0.f; }
}

// Scatter each nnz directly into the SELL-32 slab: row r lives at lane (r&31)
// of group (r>>5); entry j (per-row fill counter) at j*32 stride.
__global__ void k_scatter(const int* __restrict__ r0, const int* __restrict__ c0,
                          const float* __restrict__ d0,
                          const int* __restrict__ r1, const int* __restrict__ c1,
                          const float* __restrict__ d1) {
    int k = blockIdx.x * blockDim.x + threadIdx.x;
    if (k >= NNZ_TOT) return;
    int row, col; float w;
    if (k < NNZ_PER) { row = r0[k]; col = c0[k];                   w = d0[k]; }
    else { int j = k - NNZ_PER; row = r1[j]; col = c1[j] + N_CHILD; w = d1[j]; }
    float ew = __expf(w);
    atomicAdd(&g_z[row], ew);
    int j = atomicAdd(&g_fill[row], 1);
    if (j < MAXPAD) {
        int g = row >> 5, lane = row & 31;
        unsigned h = (unsigned)__half_as_ushort(__float2half_rn(ew));
        g_pad[g * (32 * MAXPAD) + j * 32 + lane] = ((unsigned)col << 16) | h;
    }
}

// logz per row + per-group max fill (warp-uniform loop bound for k_main)
__global__ void k_finalize() {
    int r = blockIdx.x * blockDim.x + threadIdx.x;
    if (r >= N_NODES) return;
    g_logz[r] = __logf(g_z[r]);
    int f = min(g_fill[r], MAXPAD);
    #pragma unroll
    for (int o = 16; o; o >>= 1)
        f = max(f, __shfl_xor_sync(0xFFFFFFFFu, f, o));
    if ((threadIdx.x & 31) == 0) g_grouplen[r >> 5] = f;
}

// ---------------- main compute kernel ----------------------------------------
// One block = G=4 samples; exp(ll) as half4 in 64 KB smem (2 CTAs/SM).
// One warp = one 32-row group; SELL-32 reads are fully coalesced (1 line per
// warp-LDG), loop length warp-uniform, fp32 register accumulation.
__global__ void __launch_bounds__(NTHREADS, 2)
k_main(const float* __restrict__ ll0, const float* __restrict__ ll1,
       float* __restrict__ out, int block0) {
    extern __shared__ uint2 ell[];   // [2 * N_CHILD] half4 entries
    const int tid = threadIdx.x;
    const long long s0 = (long long)(blockIdx.x + block0) * G;
    const float* p0 = ll0 + s0 * N_CHILD;
    const float* p1 = ll1 + s0 * N_CHILD;

    for (int i = tid; i < N_CHILD; i += NTHREADS) {
        float a0 = __expf(p0[i]);
        float a1 = __expf(p0[i + N_CHILD]);
        float a2 = __expf(p0[i + 2 * N_CHILD]);
        float a3 = __expf(p0[i + 3 * N_CHILD]);
        __half2 h01 = __floats2half2_rn(a0, a1);
        __half2 h23 = __floats2half2_rn(a2, a3);
        ell[i] = make_uint2(*(unsigned*)&h01, *(unsigned*)&h23);

        float b0 = __expf(p1[i]);
        float b1 = __expf(p1[i + N_CHILD]);
        float b2 = __expf(p1[i + 2 * N_CHILD]);
        float b3 = __expf(p1[i + 3 * N_CHILD]);
        __half2 g01 = __floats2half2_rn(b0, b1);
        __half2 g23 = __floats2half2_rn(b2, b3);
        ell[N_CHILD + i] = make_uint2(*(unsigned*)&g01, *(unsigned*)&g23);
    }
    __syncthreads();

    const int warp = tid >> 5, lane = tid & 31;
    #pragma unroll
    for (int pass = 0; pass < NGROUPS / NWARPS; ++pass) {   // 4 passes
        const int g   = warp + pass * NWARPS;
        const int len = g_grouplen[g];
        const unsigned* __restrict__ p = g_pad + g * (32 * MAXPAD) + lane;
        float4 acc = make_float4(0.f, 0.f, 0.f, 0.f);
        #pragma unroll 4
        for (int j = 0; j < len; ++j) {
            unsigned e = __ldg(&p[j * 32]);
            float w = __half2float(__ushort_as_half((unsigned short)(e & 0xFFFFu)));
            uint2 hv = ell[e >> 16];
            float2 v01 = __half22float2(*(__half2*)&hv.x);
            float2 v23 = __half22float2(*(__half2*)&hv.y);
            acc.x = fmaf(v01.x, w, acc.x);
            acc.y = fmaf(v01.y, w, acc.y);
            acc.z = fmaf(v23.x, w, acc.z);
            acc.w = fmaf(v23.y, w, acc.w);
        }
        const int r = g * 32 + lane;
        float lz = g_logz[r];
        float* o = out + s0 * N_NODES + r;
        o[0]           = __logf(acc.x) - lz;
        o[N_NODES]     = __logf(acc.y) - lz;
        o[2 * N_NODES] = __logf(acc.z) - lz;
        o[3 * N_NODES] = __logf(acc.w) - lz;
    }
}

// ---------------- launch ------------------------------------------------------
extern "C" void kernel_launch(void* const* d_in, const int* in_sizes, int n_in,
                              void* d_out, int out_size) {
    const float* ll0 = (const float*)d_in[0];
    const float* ll1 = (const float*)d_in[1];
    const float* w0d = (const float*)d_in[2];
    const float* w1d = (const float*)d_in[3];
    const int*   w0r = (const int*)d_in[4];
    const int*   w0c = (const int*)d_in[5];
    const int*   w1r = (const int*)d_in[6];
    const int*   w1c = (const int*)d_in[7];
    float* out = (float*)d_out;

    const int S = in_sizes[0] / N_CHILD;   // 4096
    const int nblocks = S / G;             // 1024

    const int smem_bytes = 2 * N_CHILD * (int)sizeof(uint2);  // 64 KB
    cudaFuncSetAttribute(k_main, cudaFuncAttributeMaxDynamicSharedMemorySize,
                         smem_bytes);

    k_zero<<<512, 256>>>();
    k_scatter<<<(NNZ_TOT + 255) / 256, 256>>>(w0r, w0c, w0d, w1r, w1c, w1d);
    k_finalize<<<(N_NODES + 255) / 256, 256>>>();

    // 4 sub-launches (helps ncu land on k_main; each ~256 blocks ≈ 1 wave)
    const int chunk = nblocks / 4;
    for (int c = 0; c < 4; ++c)
        k_main<<<chunk, NTHREADS, smem_bytes>>>(ll0, ll1, out, c * chunk);
}

// round 4
// speedup vs baseline: 3.4992x; 1.3698x over previous
#include <cuda_runtime.h>
#include <cuda_fp16.h>

// Fixed problem shapes
#define N_NODES   2048
#define N_CHILD   4096
#define NNZ_PER   32768
#define NNZ_TOT   (2 * NNZ_PER)
#define G         4                 // samples per compute block
#define NTHREADS  512
#define NWARPS    (NTHREADS / 32)   // 16
#define NGROUPS   (N_NODES / 32)    // 64 row-groups (one warp each)
#define MAXPAD    160               // >> Poisson(32) group max; mult of 4
#define PAD_ENTRIES (NGROUPS * 32 * MAXPAD)

// ---------------- static device scratch -------------------------------------
// SELL-32, 4-packed: group g, lane l, entry j lives at
//   g*32*MAXPAD + (j>>2)*128 + l*4 + (j&3)
// so each lane's 4 consecutive entries are one uint4 (LDG.128), and the warp's
// 32 uint4 loads cover 4 consecutive 128B lines (fully coalesced).
__device__ unsigned g_pad[PAD_ENTRIES];  // (col<<16)|fp16(exp(w)), 0 = pad
__device__ int   g_fill[N_NODES];
__device__ int   g_grouplen[NGROUPS];    // uint4 iterations = ceil(maxfill/4)
__device__ float g_z[N_NODES];
__device__ float g_logz[N_NODES];

// ---------------- prep kernels ----------------------------------------------
__global__ void k_zero() {
    int i = blockIdx.x * blockDim.x + threadIdx.x;
    int stride = gridDim.x * blockDim.x;
    uint4* p4 = (uint4*)g_pad;
    for (int k = i; k < PAD_ENTRIES / 4; k += stride)
        p4[k] = make_uint4(0u, 0u, 0u, 0u);
    if (i < N_NODES) { g_fill[i] = 0; g_z[i] = 0.f; }
}

__global__ void k_scatter(const int* __restrict__ r0, const int* __restrict__ c0,
                          const float* __restrict__ d0,
                          const int* __restrict__ r1, const int* __restrict__ c1,
                          const float* __restrict__ d1) {
    int k = blockIdx.x * blockDim.x + threadIdx.x;
    if (k >= NNZ_TOT) return;
    int row, col; float w;
    if (k < NNZ_PER) { row = r0[k]; col = c0[k];                   w = d0[k]; }
    else { int j = k - NNZ_PER; row = r1[j]; col = c1[j] + N_CHILD; w = d1[j]; }
    float ew = __expf(w);
    atomicAdd(&g_z[row], ew);
    int j = atomicAdd(&g_fill[row], 1);
    if (j < MAXPAD) {
        int g = row >> 5, lane = row & 31;
        int pos = g * (32 * MAXPAD) + (j >> 2) * 128 + lane * 4 + (j & 3);
        unsigned h = (unsigned)__half_as_ushort(__float2half_rn(ew));
        g_pad[pos] = ((unsigned)col << 16) | h;
    }
}

__global__ void k_finalize() {
    int r = blockIdx.x * blockDim.x + threadIdx.x;
    if (r >= N_NODES) return;
    g_logz[r] = __logf(g_z[r]);
    int f = min(g_fill[r], MAXPAD);
    #pragma unroll
    for (int o = 16; o; o >>= 1)
        f = max(f, __shfl_xor_sync(0xFFFFFFFFu, f, o));
    if ((threadIdx.x & 31) == 0) g_grouplen[r >> 5] = (f + 3) >> 2;
}

// ---------------- main compute kernel ----------------------------------------
// One block = G=4 samples; exp(ll) as half4 in 64 KB smem -> 3 CTAs/SM (75%).
// One warp = one 32-row group per pass; packed SELL reads: 1 LDG.128 per lane
// yields 4 entries; fp32 register accumulation.
__global__ void __launch_bounds__(NTHREADS, 3)
k_main(const float* __restrict__ ll0, const float* __restrict__ ll1,
       float* __restrict__ out) {
    extern __shared__ uint2 ell[];   // [2 * N_CHILD] half4 entries
    const int tid = threadIdx.x;
    const long long s0 = (long long)blockIdx.x * G;
    const float* p0 = ll0 + s0 * N_CHILD;
    const float* p1 = ll1 + s0 * N_CHILD;

    for (int i = tid; i < N_CHILD; i += NTHREADS) {
        float a0 = __expf(p0[i]);
        float a1 = __expf(p0[i + N_CHILD]);
        float a2 = __expf(p0[i + 2 * N_CHILD]);
        float a3 = __expf(p0[i + 3 * N_CHILD]);
        __half2 h01 = __floats2half2_rn(a0, a1);
        __half2 h23 = __floats2half2_rn(a2, a3);
        ell[i] = make_uint2(*(unsigned*)&h01, *(unsigned*)&h23);

        float b0 = __expf(p1[i]);
        float b1 = __expf(p1[i + N_CHILD]);
        float b2 = __expf(p1[i + 2 * N_CHILD]);
        float b3 = __expf(p1[i + 3 * N_CHILD]);
        __half2 g01 = __floats2half2_rn(b0, b1);
        __half2 g23 = __floats2half2_rn(b2, b3);
        ell[N_CHILD + i] = make_uint2(*(unsigned*)&g01, *(unsigned*)&g23);
    }
    __syncthreads();

    const int warp = tid >> 5, lane = tid & 31;
    #pragma unroll
    for (int pass = 0; pass < NGROUPS / NWARPS; ++pass) {   // 4 passes
        const int g    = warp + pass * NWARPS;
        const int lenb = g_grouplen[g];
        const uint4* __restrict__ p4 =
            (const uint4*)(g_pad + g * (32 * MAXPAD)) + lane;
        float4 acc = make_float4(0.f, 0.f, 0.f, 0.f);
        #pragma unroll 2
        for (int jb = 0; jb < lenb; ++jb) {
            uint4 e4 = __ldg(&p4[jb * 32]);
            #pragma unroll
            for (int q = 0; q < 4; ++q) {
                unsigned e = (q == 0) ? e4.x : (q == 1) ? e4.y
                           : (q == 2) ? e4.z : e4.w;
                float w = __half2float(__ushort_as_half((unsigned short)(e & 0xFFFFu)));
                uint2 hv = ell[e >> 16];
                float2 v01 = __half22float2(*(__half2*)&hv.x);
                float2 v23 = __half22float2(*(__half2*)&hv.y);
                acc.x = fmaf(v01.x, w, acc.x);
                acc.y = fmaf(v01.y, w, acc.y);
                acc.z = fmaf(v23.x, w, acc.z);
                acc.w = fmaf(v23.y, w, acc.w);
            }
        }
        const int r = g * 32 + lane;
        float lz = g_logz[r];
        float* o = out + s0 * N_NODES + r;
        o[0]           = __logf(acc.x) - lz;
        o[N_NODES]     = __logf(acc.y) - lz;
        o[2 * N_NODES] = __logf(acc.z) - lz;
        o[3 * N_NODES] = __logf(acc.w) - lz;
    }
}

// ---------------- launch ------------------------------------------------------
extern "C" void kernel_launch(void* const* d_in, const int* in_sizes, int n_in,
                              void* d_out, int out_size) {
    const float* ll0 = (const float*)d_in[0];
    const float* ll1 = (const float*)d_in[1];
    const float* w0d = (const float*)d_in[2];
    const float* w1d = (const float*)d_in[3];
    const int*   w0r = (const int*)d_in[4];
    const int*   w0c = (const int*)d_in[5];
    const int*   w1r = (const int*)d_in[6];
    const int*   w1c = (const int*)d_in[7];
    float* out = (float*)d_out;

    const int S = in_sizes[0] / N_CHILD;   // 4096
    const int nblocks = S / G;             // 1024

    const int smem_bytes = 2 * N_CHILD * (int)sizeof(uint2);  // 64 KB
    cudaFuncSetAttribute(k_main, cudaFuncAttributeMaxDynamicSharedMemorySize,
                         smem_bytes);

    k_zero<<<512, 256>>>();
    k_scatter<<<(NNZ_TOT + 255) / 256, 256>>>(w0r, w0c, w0d, w1r, w1c, w1d);
    k_finalize<<<(N_NODES + 255) / 256, 256>>>();
    k_main<<<nblocks, NTHREADS, smem_bytes>>>(ll0, ll1, out);
}